// round 12
// baseline (speedup 1.0000x reference)
#include <cuda_runtime.h>
#include <cuda_bf16.h>
#include <cstdint>

// ---------------------------------------------------------------------------
// GIN GraphEncoder, round 11:
//   - MLP rebalanced: 4 warps x (64x64) warp tiles -> halves smem crossbar
//     bytes per MMA (was 8 warps x 32x64, LDS-crossbar-bound)
//   - gather emits (x + agg) directly (GIN eps=0)
//   - fused 2-phase MLP per layer, H staged in smem as tf32
// edge_index / batch are int32 (jax default, x64 disabled).
// ---------------------------------------------------------------------------

static constexpr int N_NODES  = 100000;
static constexpr int N_EDGES  = 1600000;
static constexpr int D        = 128;
static constexpr int N_LAYERS = 3;
static constexpr int N_GRAPHS = 128;

// Scratch (__device__ globals per alloc-free rule)
__device__ __align__(16) float g_xa  [(size_t)N_NODES * D];  // x + agg
__device__ __align__(16) float g_xcur[(size_t)N_NODES * D];  // layer output
__device__ int g_counts  [N_NODES];
__device__ int g_rowstart[N_NODES + 1];
__device__ int g_cursor  [N_NODES];
__device__ int g_csr_src [N_EDGES];

// ---------------------------------------------------------------------------
// CSR build: histogram -> scan -> fill
// ---------------------------------------------------------------------------
__global__ void hist_kernel(const int* __restrict__ ei, int* __restrict__ counts) {
    int e = blockIdx.x * blockDim.x + threadIdx.x;
    if (e < N_EDGES) atomicAdd(&counts[ei[N_EDGES + e]], 1);
}

__global__ void scan_kernel(const int* __restrict__ counts,
                            int* __restrict__ rowstart, int* __restrict__ cursor) {
    __shared__ int tsum[1024];
    const int t = threadIdx.x;
    const int CHUNK = (N_NODES + 1023) / 1024;  // 98
    const int lo = t * CHUNK;
    const int hi = min(lo + CHUNK, N_NODES);
    int s = 0;
    for (int i = lo; i < hi; i++) s += counts[i];
    tsum[t] = s;
    __syncthreads();
    for (int st = 1; st < 1024; st <<= 1) {
        int v = (t >= st) ? tsum[t - st] : 0;
        __syncthreads();
        tsum[t] += v;
        __syncthreads();
    }
    int run = (t > 0) ? tsum[t - 1] : 0;
    for (int i = lo; i < hi; i++) {
        rowstart[i] = run;
        cursor[i]   = run;
        run += counts[i];
    }
    if (t == 0) rowstart[N_NODES] = N_EDGES;
}

__global__ void fill_kernel(const int* __restrict__ ei,
                            int* __restrict__ cursor, int* __restrict__ csr_src) {
    int e = blockIdx.x * blockDim.x + threadIdx.x;
    if (e < N_EDGES) {
        int s = ei[e];
        int d = ei[N_EDGES + e];
        int slot = atomicAdd(&cursor[d], 1);
        csr_src[slot] = s;
    }
}

// ---------------------------------------------------------------------------
// Gather: one warp per node; lane owns 4 dims. Accumulator seeded with the
// node's own row (GIN eps=0). Deterministic per dim.
// ---------------------------------------------------------------------------
__global__ void gather_kernel(const float* __restrict__ x,
                              const int* __restrict__ rowstart,
                              const int* __restrict__ csr_src,
                              float* __restrict__ xa) {
    int wid = (blockIdx.x * blockDim.x + threadIdx.x) >> 5;
    if (wid >= N_NODES) return;
    int lane = threadIdx.x & 31;
    int beg = rowstart[wid], end = rowstart[wid + 1];
    float4 acc = *reinterpret_cast<const float4*>(x + (size_t)wid * D + lane * 4);
    int i = beg;
    for (; i + 2 <= end; i += 2) {
        int s0 = csr_src[i], s1 = csr_src[i + 1];
        float4 v0 = *reinterpret_cast<const float4*>(x + (size_t)s0 * D + lane * 4);
        float4 v1 = *reinterpret_cast<const float4*>(x + (size_t)s1 * D + lane * 4);
        acc.x += v0.x + v1.x; acc.y += v0.y + v1.y;
        acc.z += v0.z + v1.z; acc.w += v0.w + v1.w;
    }
    if (i < end) {
        int s0 = csr_src[i];
        float4 v0 = *reinterpret_cast<const float4*>(x + (size_t)s0 * D + lane * 4);
        acc.x += v0.x; acc.y += v0.y; acc.z += v0.z; acc.w += v0.w;
    }
    *reinterpret_cast<float4*>(xa + (size_t)wid * D + lane * 4) = acc;
}

// ---------------------------------------------------------------------------
// Fused MLP: C = relu(A@W1+b1)@W2 + b2, tf32 tensor cores.
// CTA: 128 rows x 128 cols; 4 warps in 2x2 grid, warp tile 64x64, BK=32.
// H (128x128) staged in smem as tf32 between phases.
// ---------------------------------------------------------------------------
__device__ __forceinline__ uint32_t f2tf32(float f) {
    uint32_t r;
    asm("cvt.rna.tf32.f32 %0, %1;" : "=r"(r) : "f"(f));
    return r;
}

__device__ __forceinline__ void mma_tf32(float* c, const uint32_t* a, const uint32_t* b) {
    asm volatile(
        "mma.sync.aligned.m16n8k8.row.col.f32.tf32.tf32.f32 "
        "{%0,%1,%2,%3}, {%4,%5,%6,%7}, {%8,%9}, {%0,%1,%2,%3};"
        : "+f"(c[0]), "+f"(c[1]), "+f"(c[2]), "+f"(c[3])
        : "r"(a[0]), "r"(a[1]), "r"(a[2]), "r"(a[3]), "r"(b[0]), "r"(b[1]));
}

static constexpr int SA_LD = 36;    // (r*36+c)%32 = (4r+c)%32 conflict-free
static constexpr int SW_LD = 136;   // (k*136+c)%32 = (8k+c)%32 conflict-free
static constexpr int SH_LD = 132;   // (r*132+c)%32 = (4r+c)%32 conflict-free
static constexpr int SA_WORDS = 128 * SA_LD;             // 4608
static constexpr int SW_WORDS = 32 * SW_LD;              // 4352
static constexpr int SH_WORDS = 128 * SH_LD;             // 16896
static constexpr int MLP_SMEM_BYTES = (SA_WORDS + SW_WORDS + SH_WORDS) * 4;  // 103424

static constexpr int MLP_THREADS = 128;

__global__ __launch_bounds__(MLP_THREADS)
void mlp_kernel(const float* __restrict__ A,
                const float* __restrict__ W1, const float* __restrict__ b1,
                const float* __restrict__ W2, const float* __restrict__ b2,
                float* __restrict__ C, int M) {
    extern __shared__ uint32_t smem[];
    uint32_t* sA = smem;
    uint32_t* sW = smem + SA_WORDS;
    uint32_t* sH = smem + SA_WORDS + SW_WORDS;

    constexpr int BM = 128;
    constexpr int BK = 32;

    const int t      = threadIdx.x;
    const int warp   = t >> 5;
    const int lane   = t & 31;
    const int warp_m = warp & 1;   // 64-row band
    const int warp_n = warp >> 1;  // 64-col band
    const int row0   = blockIdx.x * BM;
    const int qr     = lane >> 2;  // 0..7
    const int qc     = lane & 3;   // 0..3

    float acc[4][8][4];
#pragma unroll
    for (int mt = 0; mt < 4; mt++)
#pragma unroll
        for (int nt = 0; nt < 8; nt++)
#pragma unroll
            for (int k = 0; k < 4; k++) acc[mt][nt][k] = 0.f;

    // ---- phase 1: acc = A @ W1 ----
    for (int k0 = 0; k0 < D; k0 += BK) {
        // A tile: 128 x 32 floats = 1024 float4 -> 8 iters/thread
#pragma unroll
        for (int i = t; i < BM * (BK / 4); i += MLP_THREADS) {
            int r = i >> 3;
            int c = (i & 7) * 4;
            float4 v = make_float4(0.f, 0.f, 0.f, 0.f);
            int gr = row0 + r;
            if (gr < M) v = *reinterpret_cast<const float4*>(A + (size_t)gr * D + k0 + c);
            uint32_t* p = &sA[r * SA_LD + c];
            p[0] = f2tf32(v.x); p[1] = f2tf32(v.y); p[2] = f2tf32(v.z); p[3] = f2tf32(v.w);
        }
        // W tile: 32 x 128 floats = 1024 float4 -> 8 iters/thread
#pragma unroll
        for (int i = t; i < BK * (D / 4); i += MLP_THREADS) {
            int r = i >> 5;
            int c = (i & 31) * 4;
            float4 v = *reinterpret_cast<const float4*>(W1 + (size_t)(k0 + r) * D + c);
            uint32_t* p = &sW[r * SW_LD + c];
            p[0] = f2tf32(v.x); p[1] = f2tf32(v.y); p[2] = f2tf32(v.z); p[3] = f2tf32(v.w);
        }
        __syncthreads();

#pragma unroll
        for (int ks = 0; ks < BK; ks += 8) {
            uint32_t af[4][4], bf[8][2];
#pragma unroll
            for (int mt = 0; mt < 4; mt++) {
                int rb = warp_m * 64 + mt * 16;
                af[mt][0] = sA[(rb + qr)     * SA_LD + ks + qc];
                af[mt][1] = sA[(rb + qr + 8) * SA_LD + ks + qc];
                af[mt][2] = sA[(rb + qr)     * SA_LD + ks + qc + 4];
                af[mt][3] = sA[(rb + qr + 8) * SA_LD + ks + qc + 4];
            }
#pragma unroll
            for (int nt = 0; nt < 8; nt++) {
                int cb = warp_n * 64 + nt * 8 + qr;
                bf[nt][0] = sW[(ks + qc)     * SW_LD + cb];
                bf[nt][1] = sW[(ks + qc + 4) * SW_LD + cb];
            }
#pragma unroll
            for (int mt = 0; mt < 4; mt++)
#pragma unroll
                for (int nt = 0; nt < 8; nt++)
                    mma_tf32(acc[mt][nt], af[mt], bf[nt]);
        }
        __syncthreads();
    }

    // ---- H = relu(acc + b1) -> smem (tf32) ----
#pragma unroll
    for (int nt = 0; nt < 8; nt++) {
        int cb = warp_n * 64 + nt * 8 + 2 * qc;
        float bx = __ldg(&b1[cb]);
        float by = __ldg(&b1[cb + 1]);
#pragma unroll
        for (int mt = 0; mt < 4; mt++) {
            int r = warp_m * 64 + mt * 16 + qr;
            sH[r * SH_LD + cb]           = f2tf32(fmaxf(acc[mt][nt][0] + bx, 0.f));
            sH[r * SH_LD + cb + 1]       = f2tf32(fmaxf(acc[mt][nt][1] + by, 0.f));
            sH[(r + 8) * SH_LD + cb]     = f2tf32(fmaxf(acc[mt][nt][2] + bx, 0.f));
            sH[(r + 8) * SH_LD + cb + 1] = f2tf32(fmaxf(acc[mt][nt][3] + by, 0.f));
        }
    }
    __syncthreads();

    // ---- phase 2: acc = H @ W2 ----
#pragma unroll
    for (int mt = 0; mt < 4; mt++)
#pragma unroll
        for (int nt = 0; nt < 8; nt++)
#pragma unroll
            for (int k = 0; k < 4; k++) acc[mt][nt][k] = 0.f;

    for (int k0 = 0; k0 < D; k0 += BK) {
#pragma unroll
        for (int i = t; i < BK * (D / 4); i += MLP_THREADS) {
            int r = i >> 5;
            int c = (i & 31) * 4;
            float4 v = *reinterpret_cast<const float4*>(W2 + (size_t)(k0 + r) * D + c);
            uint32_t* p = &sW[r * SW_LD + c];
            p[0] = f2tf32(v.x); p[1] = f2tf32(v.y); p[2] = f2tf32(v.z); p[3] = f2tf32(v.w);
        }
        __syncthreads();

#pragma unroll
        for (int ks = 0; ks < BK; ks += 8) {
            uint32_t af[4][4], bf[8][2];
#pragma unroll
            for (int mt = 0; mt < 4; mt++) {
                int rb = warp_m * 64 + mt * 16;
                af[mt][0] = sH[(rb + qr)     * SH_LD + k0 + ks + qc];
                af[mt][1] = sH[(rb + qr + 8) * SH_LD + k0 + ks + qc];
                af[mt][2] = sH[(rb + qr)     * SH_LD + k0 + ks + qc + 4];
                af[mt][3] = sH[(rb + qr + 8) * SH_LD + k0 + ks + qc + 4];
            }
#pragma unroll
            for (int nt = 0; nt < 8; nt++) {
                int cb = warp_n * 64 + nt * 8 + qr;
                bf[nt][0] = sW[(ks + qc)     * SW_LD + cb];
                bf[nt][1] = sW[(ks + qc + 4) * SW_LD + cb];
            }
#pragma unroll
            for (int mt = 0; mt < 4; mt++)
#pragma unroll
                for (int nt = 0; nt < 8; nt++)
                    mma_tf32(acc[mt][nt], af[mt], bf[nt]);
        }
        __syncthreads();
    }

    // ---- epilogue: C = acc + b2 ----
#pragma unroll
    for (int nt = 0; nt < 8; nt++) {
        int cb = warp_n * 64 + nt * 8 + 2 * qc;
        float bx = __ldg(&b2[cb]);
        float by = __ldg(&b2[cb + 1]);
#pragma unroll
        for (int mt = 0; mt < 4; mt++) {
            int r0 = row0 + warp_m * 64 + mt * 16 + qr;
            float2 v0, v1;
            v0.x = acc[mt][nt][0] + bx; v0.y = acc[mt][nt][1] + by;
            v1.x = acc[mt][nt][2] + bx; v1.y = acc[mt][nt][3] + by;
            if (r0 < M)     *reinterpret_cast<float2*>(C + (size_t)r0 * D + cb)       = v0;
            if (r0 + 8 < M) *reinterpret_cast<float2*>(C + (size_t)(r0 + 8) * D + cb) = v1;
        }
    }
}

// ---------------------------------------------------------------------------
// Pool: 400 CTAs x 128 threads; run-length accumulate per dim, atomic flush
// on graph-id change (batch sorted).
// ---------------------------------------------------------------------------
__global__ void pool_kernel(const float* __restrict__ x,
                            const int* __restrict__ batch,
                            float* __restrict__ out) {
    constexpr int NCTA  = 400;
    constexpr int CHUNK = (N_NODES + NCTA - 1) / NCTA;  // 250
    int d  = threadIdx.x;
    int r0 = blockIdx.x * CHUNK;
    int r1 = min(r0 + CHUNK, N_NODES);
    if (r0 >= r1) return;
    int gcur = batch[r0];
    float s = 0.f;
    for (int r = r0; r < r1; r++) {
        int g = batch[r];
        if (g != gcur) {
            atomicAdd(&out[gcur * D + d], s);
            s = 0.f;
            gcur = g;
        }
        s += x[(size_t)r * D + d];
    }
    atomicAdd(&out[gcur * D + d], s);
}

// ---------------------------------------------------------------------------
// Launch. Inputs identified by element count:
//   x: 12,800,000 | edge_index: 3,200,000 (int32) | batch: 100,000 (int32)
//   W1/W2: 49,152 (first = W1) | b1/b2: 384 (first = b1)
// ---------------------------------------------------------------------------
extern "C" void kernel_launch(void* const* d_in, const int* in_sizes, int n_in,
                              void* d_out, int out_size) {
    const float *x_in = nullptr, *W1 = nullptr, *b1 = nullptr, *W2 = nullptr, *b2 = nullptr;
    const int *ei = nullptr, *batch = nullptr;

    for (int i = 0; i < n_in; i++) {
        int s = in_sizes[i];
        if (s == N_NODES * D)            x_in  = (const float*)d_in[i];
        else if (s == 2 * N_EDGES)       ei    = (const int*)d_in[i];
        else if (s == N_NODES)           batch = (const int*)d_in[i];
        else if (s == N_LAYERS * D * D) { if (!W1) W1 = (const float*)d_in[i]; else W2 = (const float*)d_in[i]; }
        else if (s == N_LAYERS * D)     { if (!b1) b1 = (const float*)d_in[i]; else b2 = (const float*)d_in[i]; }
    }
    float* out = (float*)d_out;

    float* xa;   cudaGetSymbolAddress((void**)&xa,   g_xa);
    float* xcur; cudaGetSymbolAddress((void**)&xcur, g_xcur);
    int* counts;   cudaGetSymbolAddress((void**)&counts,   g_counts);
    int* rowstart; cudaGetSymbolAddress((void**)&rowstart, g_rowstart);
    int* cursor;   cudaGetSymbolAddress((void**)&cursor,   g_cursor);
    int* csr_src;  cudaGetSymbolAddress((void**)&csr_src,  g_csr_src);

    cudaFuncSetAttribute(mlp_kernel, cudaFuncAttributeMaxDynamicSharedMemorySize,
                         MLP_SMEM_BYTES);

    const int edge_blocks = (N_EDGES + 255) / 256;
    const int gemm_blocks = (N_NODES + 127) / 128;
    const int gat_blocks  = (N_NODES * 32 + 255) / 256;

    // CSR build (per call; deterministic structure)
    cudaMemsetAsync(counts, 0, N_NODES * sizeof(int));
    hist_kernel<<<edge_blocks, 256>>>(ei, counts);
    scan_kernel<<<1, 1024>>>(counts, rowstart, cursor);
    fill_kernel<<<edge_blocks, 256>>>(ei, cursor, csr_src);

    const float* xsrc = x_in;
    for (int i = 0; i < N_LAYERS; i++) {
        gather_kernel<<<gat_blocks, 256>>>(xsrc, rowstart, csr_src, xa);
        mlp_kernel<<<gemm_blocks, MLP_THREADS, MLP_SMEM_BYTES>>>(
            xa, W1 + (size_t)i * D * D, b1 + i * D,
            W2 + (size_t)i * D * D, b2 + i * D, xcur, N_NODES);
        xsrc = xcur;
    }

    cudaMemsetAsync(out, 0, (size_t)N_GRAPHS * D * sizeof(float));
    pool_kernel<<<400, 128>>>(xcur, batch, out);
}

// round 14
// speedup vs baseline: 1.0180x; 1.0180x over previous
#include <cuda_runtime.h>
#include <cuda_bf16.h>
#include <cstdint>

// ---------------------------------------------------------------------------
// GIN GraphEncoder, round 13:
//   - MLP software-pipelined: next A tile (phase1) / W2 tile (phase2)
//     prefetched into registers while MMAs consume current smem tile.
//     256 thr, 8 warps (2x4) of 64x32 tiles, <=128 regs -> 2 CTAs/SM.
//   - gather emits (x + agg) directly (GIN eps=0)
//   - fused 2-phase MLP per layer, H staged in smem as tf32
// edge_index / batch are int32 (jax default, x64 disabled).
// ---------------------------------------------------------------------------

static constexpr int N_NODES  = 100000;
static constexpr int N_EDGES  = 1600000;
static constexpr int D        = 128;
static constexpr int N_LAYERS = 3;
static constexpr int N_GRAPHS = 128;

// Scratch (__device__ globals per alloc-free rule)
__device__ __align__(16) float g_xa  [(size_t)N_NODES * D];  // x + agg
__device__ __align__(16) float g_xcur[(size_t)N_NODES * D];  // layer output
__device__ int g_counts  [N_NODES];
__device__ int g_rowstart[N_NODES + 1];
__device__ int g_cursor  [N_NODES];
__device__ int g_csr_src [N_EDGES];

// ---------------------------------------------------------------------------
// CSR build: histogram -> scan -> fill
// ---------------------------------------------------------------------------
__global__ void hist_kernel(const int* __restrict__ ei, int* __restrict__ counts) {
    int e = blockIdx.x * blockDim.x + threadIdx.x;
    if (e < N_EDGES) atomicAdd(&counts[ei[N_EDGES + e]], 1);
}

__global__ void scan_kernel(const int* __restrict__ counts,
                            int* __restrict__ rowstart, int* __restrict__ cursor) {
    __shared__ int tsum[1024];
    const int t = threadIdx.x;
    const int CHUNK = (N_NODES + 1023) / 1024;  // 98
    const int lo = t * CHUNK;
    const int hi = min(lo + CHUNK, N_NODES);
    int s = 0;
    for (int i = lo; i < hi; i++) s += counts[i];
    tsum[t] = s;
    __syncthreads();
    for (int st = 1; st < 1024; st <<= 1) {
        int v = (t >= st) ? tsum[t - st] : 0;
        __syncthreads();
        tsum[t] += v;
        __syncthreads();
    }
    int run = (t > 0) ? tsum[t - 1] : 0;
    for (int i = lo; i < hi; i++) {
        rowstart[i] = run;
        cursor[i]   = run;
        run += counts[i];
    }
    if (t == 0) rowstart[N_NODES] = N_EDGES;
}

__global__ void fill_kernel(const int* __restrict__ ei,
                            int* __restrict__ cursor, int* __restrict__ csr_src) {
    int e = blockIdx.x * blockDim.x + threadIdx.x;
    if (e < N_EDGES) {
        int s = ei[e];
        int d = ei[N_EDGES + e];
        int slot = atomicAdd(&cursor[d], 1);
        csr_src[slot] = s;
    }
}

// ---------------------------------------------------------------------------
// Gather: one warp per node; lane owns 4 dims. Accumulator seeded with the
// node's own row (GIN eps=0). Deterministic per dim.
// ---------------------------------------------------------------------------
__global__ void gather_kernel(const float* __restrict__ x,
                              const int* __restrict__ rowstart,
                              const int* __restrict__ csr_src,
                              float* __restrict__ xa) {
    int wid = (blockIdx.x * blockDim.x + threadIdx.x) >> 5;
    if (wid >= N_NODES) return;
    int lane = threadIdx.x & 31;
    int beg = rowstart[wid], end = rowstart[wid + 1];
    float4 acc = *reinterpret_cast<const float4*>(x + (size_t)wid * D + lane * 4);
    int i = beg;
    for (; i + 2 <= end; i += 2) {
        int s0 = csr_src[i], s1 = csr_src[i + 1];
        float4 v0 = *reinterpret_cast<const float4*>(x + (size_t)s0 * D + lane * 4);
        float4 v1 = *reinterpret_cast<const float4*>(x + (size_t)s1 * D + lane * 4);
        acc.x += v0.x + v1.x; acc.y += v0.y + v1.y;
        acc.z += v0.z + v1.z; acc.w += v0.w + v1.w;
    }
    if (i < end) {
        int s0 = csr_src[i];
        float4 v0 = *reinterpret_cast<const float4*>(x + (size_t)s0 * D + lane * 4);
        acc.x += v0.x; acc.y += v0.y; acc.z += v0.z; acc.w += v0.w;
    }
    *reinterpret_cast<float4*>(xa + (size_t)wid * D + lane * 4) = acc;
}

// ---------------------------------------------------------------------------
// Fused MLP: C = relu(A@W1+b1)@W2 + b2, tf32 tensor cores, pipelined.
// CTA: 128x128; 8 warps in 2x4 grid, warp tile 64x32, BK=32.
// H (128x128) staged in smem as tf32 between phases.
// ---------------------------------------------------------------------------
__device__ __forceinline__ uint32_t f2tf32(float f) {
    uint32_t r;
    asm("cvt.rna.tf32.f32 %0, %1;" : "=r"(r) : "f"(f));
    return r;
}

__device__ __forceinline__ void mma_tf32(float* c, const uint32_t* a, const uint32_t* b) {
    asm volatile(
        "mma.sync.aligned.m16n8k8.row.col.f32.tf32.tf32.f32 "
        "{%0,%1,%2,%3}, {%4,%5,%6,%7}, {%8,%9}, {%0,%1,%2,%3};"
        : "+f"(c[0]), "+f"(c[1]), "+f"(c[2]), "+f"(c[3])
        : "r"(a[0]), "r"(a[1]), "r"(a[2]), "r"(a[3]), "r"(b[0]), "r"(b[1]));
}

static constexpr int SA_LD = 36;    // (r*36+c)%32 = (4r+c)%32 conflict-free
static constexpr int SW_LD = 136;   // (k*136+c)%32 = (8k+c)%32 conflict-free
static constexpr int SH_LD = 132;   // (r*132+c)%32 = (4r+c)%32 conflict-free
static constexpr int SA_WORDS = 128 * SA_LD;             // 4608
static constexpr int SW_WORDS = 32 * SW_LD;              // 4352
static constexpr int SH_WORDS = 128 * SH_LD;             // 16896
static constexpr int MLP_SMEM_BYTES = (SA_WORDS + SW_WORDS + SH_WORDS) * 4;  // 103424

static constexpr int MLP_THREADS = 256;

__global__ __launch_bounds__(MLP_THREADS, 2)
void mlp_kernel(const float* __restrict__ A,
                const float* __restrict__ W1, const float* __restrict__ b1,
                const float* __restrict__ W2, const float* __restrict__ b2,
                float* __restrict__ C, int M) {
    extern __shared__ uint32_t smem[];
    uint32_t* sA = smem;
    uint32_t* sW = smem + SA_WORDS;
    uint32_t* sH = smem + SA_WORDS + SW_WORDS;

    constexpr int BK = 32;

    const int t      = threadIdx.x;
    const int warp   = t >> 5;
    const int lane   = t & 31;
    const int warp_m = warp & 1;   // 64-row band
    const int warp_n = warp >> 1;  // 32-col band (0..3)
    const int row0   = blockIdx.x * 128;
    const int qr     = lane >> 2;  // 0..7
    const int qc     = lane & 3;   // 0..3

    // per-thread tile-load coords (A: 1024 f4, 4/thread; W: 1024 f4, 4/thread)
    const int a_r = t >> 3;              // + j*32 rows
    const int a_c = (t & 7) * 4;
    const int w_r = t >> 5;              // + j*8 rows
    const int w_c = (t & 31) * 4;

    float4 rp[4];  // prefetch regs (A tiles in phase 1, W2 tiles in phase 2)

    float acc[4][4][4];
#pragma unroll
    for (int mt = 0; mt < 4; mt++)
#pragma unroll
        for (int nt = 0; nt < 4; nt++)
#pragma unroll
            for (int k = 0; k < 4; k++) acc[mt][nt][k] = 0.f;

    // ---- phase 1: acc = A @ W1 (A tiles prefetched to regs) ----
#pragma unroll
    for (int j = 0; j < 4; j++) {
        int gr = row0 + a_r + j * 32;
        rp[j] = (gr < M) ? *reinterpret_cast<const float4*>(A + (size_t)gr * D + a_c)
                         : make_float4(0.f, 0.f, 0.f, 0.f);
    }
#pragma unroll
    for (int j = 0; j < 4; j++) {
        uint32_t* p = &sA[(a_r + j * 32) * SA_LD + a_c];
        p[0] = f2tf32(rp[j].x); p[1] = f2tf32(rp[j].y);
        p[2] = f2tf32(rp[j].z); p[3] = f2tf32(rp[j].w);
    }
#pragma unroll
    for (int j = 0; j < 4; j++) {
        float4 v = *reinterpret_cast<const float4*>(W1 + (size_t)(w_r + j * 8) * D + w_c);
        uint32_t* p = &sW[(w_r + j * 8) * SW_LD + w_c];
        p[0] = f2tf32(v.x); p[1] = f2tf32(v.y); p[2] = f2tf32(v.z); p[3] = f2tf32(v.w);
    }
    __syncthreads();

    for (int k0i = 0; k0i < 4; k0i++) {
        if (k0i < 3) {
            int k0n = (k0i + 1) * BK;
#pragma unroll
            for (int j = 0; j < 4; j++) {
                int gr = row0 + a_r + j * 32;
                rp[j] = (gr < M)
                    ? *reinterpret_cast<const float4*>(A + (size_t)gr * D + k0n + a_c)
                    : make_float4(0.f, 0.f, 0.f, 0.f);
            }
        }
#pragma unroll
        for (int ks = 0; ks < BK; ks += 8) {
            uint32_t af[4][4], bf[4][2];
#pragma unroll
            for (int mt = 0; mt < 4; mt++) {
                int rb = warp_m * 64 + mt * 16;
                af[mt][0] = sA[(rb + qr)     * SA_LD + ks + qc];
                af[mt][1] = sA[(rb + qr + 8) * SA_LD + ks + qc];
                af[mt][2] = sA[(rb + qr)     * SA_LD + ks + qc + 4];
                af[mt][3] = sA[(rb + qr + 8) * SA_LD + ks + qc + 4];
            }
#pragma unroll
            for (int nt = 0; nt < 4; nt++) {
                int cb = warp_n * 32 + nt * 8 + qr;
                bf[nt][0] = sW[(ks + qc)     * SW_LD + cb];
                bf[nt][1] = sW[(ks + qc + 4) * SW_LD + cb];
            }
#pragma unroll
            for (int mt = 0; mt < 4; mt++)
#pragma unroll
                for (int nt = 0; nt < 4; nt++)
                    mma_tf32(acc[mt][nt], af[mt], bf[nt]);
        }
        __syncthreads();
        if (k0i < 3) {
            int k0n = (k0i + 1) * BK;
#pragma unroll
            for (int j = 0; j < 4; j++) {
                uint32_t* p = &sA[(a_r + j * 32) * SA_LD + a_c];
                p[0] = f2tf32(rp[j].x); p[1] = f2tf32(rp[j].y);
                p[2] = f2tf32(rp[j].z); p[3] = f2tf32(rp[j].w);
            }
#pragma unroll
            for (int j = 0; j < 4; j++) {
                float4 v = *reinterpret_cast<const float4*>(
                    W1 + (size_t)(k0n + w_r + j * 8) * D + w_c);
                uint32_t* p = &sW[(w_r + j * 8) * SW_LD + w_c];
                p[0] = f2tf32(v.x); p[1] = f2tf32(v.y);
                p[2] = f2tf32(v.z); p[3] = f2tf32(v.w);
            }
            __syncthreads();
        }
    }

    // ---- H = relu(acc + b1) -> smem (tf32); then preload W2 tile 0 ----
#pragma unroll
    for (int nt = 0; nt < 4; nt++) {
        int cb = warp_n * 32 + nt * 8 + 2 * qc;
        float bx = __ldg(&b1[cb]);
        float by = __ldg(&b1[cb + 1]);
#pragma unroll
        for (int mt = 0; mt < 4; mt++) {
            int r = warp_m * 64 + mt * 16 + qr;
            sH[r * SH_LD + cb]           = f2tf32(fmaxf(acc[mt][nt][0] + bx, 0.f));
            sH[r * SH_LD + cb + 1]       = f2tf32(fmaxf(acc[mt][nt][1] + by, 0.f));
            sH[(r + 8) * SH_LD + cb]     = f2tf32(fmaxf(acc[mt][nt][2] + bx, 0.f));
            sH[(r + 8) * SH_LD + cb + 1] = f2tf32(fmaxf(acc[mt][nt][3] + by, 0.f));
        }
    }
#pragma unroll
    for (int j = 0; j < 4; j++) {
        float4 v = *reinterpret_cast<const float4*>(W2 + (size_t)(w_r + j * 8) * D + w_c);
        uint32_t* p = &sW[(w_r + j * 8) * SW_LD + w_c];
        p[0] = f2tf32(v.x); p[1] = f2tf32(v.y); p[2] = f2tf32(v.z); p[3] = f2tf32(v.w);
    }
    __syncthreads();

    // ---- phase 2: acc = H @ W2 (W2 tiles prefetched to regs) ----
#pragma unroll
    for (int mt = 0; mt < 4; mt++)
#pragma unroll
        for (int nt = 0; nt < 4; nt++)
#pragma unroll
            for (int k = 0; k < 4; k++) acc[mt][nt][k] = 0.f;

    for (int k0i = 0; k0i < 4; k0i++) {
        int k0 = k0i * BK;
        if (k0i < 3) {
            int k0n = k0 + BK;
#pragma unroll
            for (int j = 0; j < 4; j++)
                rp[j] = *reinterpret_cast<const float4*>(
                    W2 + (size_t)(k0n + w_r + j * 8) * D + w_c);
        }
#pragma unroll
        for (int ks = 0; ks < BK; ks += 8) {
            uint32_t af[4][4], bf[4][2];
#pragma unroll
            for (int mt = 0; mt < 4; mt++) {
                int rb = warp_m * 64 + mt * 16;
                af[mt][0] = sH[(rb + qr)     * SH_LD + k0 + ks + qc];
                af[mt][1] = sH[(rb + qr + 8) * SH_LD + k0 + ks + qc];
                af[mt][2] = sH[(rb + qr)     * SH_LD + k0 + ks + qc + 4];
                af[mt][3] = sH[(rb + qr + 8) * SH_LD + k0 + ks + qc + 4];
            }
#pragma unroll
            for (int nt = 0; nt < 4; nt++) {
                int cb = warp_n * 32 + nt * 8 + qr;
                bf[nt][0] = sW[(ks + qc)     * SW_LD + cb];
                bf[nt][1] = sW[(ks + qc + 4) * SW_LD + cb];
            }
#pragma unroll
            for (int mt = 0; mt < 4; mt++)
#pragma unroll
                for (int nt = 0; nt < 4; nt++)
                    mma_tf32(acc[mt][nt], af[mt], bf[nt]);
        }
        __syncthreads();
        if (k0i < 3) {
#pragma unroll
            for (int j = 0; j < 4; j++) {
                uint32_t* p = &sW[(w_r + j * 8) * SW_LD + w_c];
                p[0] = f2tf32(rp[j].x); p[1] = f2tf32(rp[j].y);
                p[2] = f2tf32(rp[j].z); p[3] = f2tf32(rp[j].w);
            }
            __syncthreads();
        }
    }

    // ---- epilogue: C = acc + b2 ----
#pragma unroll
    for (int nt = 0; nt < 4; nt++) {
        int cb = warp_n * 32 + nt * 8 + 2 * qc;
        float bx = __ldg(&b2[cb]);
        float by = __ldg(&b2[cb + 1]);
#pragma unroll
        for (int mt = 0; mt < 4; mt++) {
            int r0 = row0 + warp_m * 64 + mt * 16 + qr;
            float2 v0, v1;
            v0.x = acc[mt][nt][0] + bx; v0.y = acc[mt][nt][1] + by;
            v1.x = acc[mt][nt][2] + bx; v1.y = acc[mt][nt][3] + by;
            if (r0 < M)     *reinterpret_cast<float2*>(C + (size_t)r0 * D + cb)       = v0;
            if (r0 + 8 < M) *reinterpret_cast<float2*>(C + (size_t)(r0 + 8) * D + cb) = v1;
        }
    }
}

// ---------------------------------------------------------------------------
// Pool: 400 CTAs x 128 threads; run-length accumulate per dim, atomic flush
// on graph-id change (batch sorted).
// ---------------------------------------------------------------------------
__global__ void pool_kernel(const float* __restrict__ x,
                            const int* __restrict__ batch,
                            float* __restrict__ out) {
    constexpr int NCTA  = 400;
    constexpr int CHUNK = (N_NODES + NCTA - 1) / NCTA;  // 250
    int d  = threadIdx.x;
    int r0 = blockIdx.x * CHUNK;
    int r1 = min(r0 + CHUNK, N_NODES);
    if (r0 >= r1) return;
    int gcur = batch[r0];
    float s = 0.f;
    for (int r = r0; r < r1; r++) {
        int g = batch[r];
        if (g != gcur) {
            atomicAdd(&out[gcur * D + d], s);
            s = 0.f;
            gcur = g;
        }
        s += x[(size_t)r * D + d];
    }
    atomicAdd(&out[gcur * D + d], s);
}

// ---------------------------------------------------------------------------
// Launch. Inputs identified by element count:
//   x: 12,800,000 | edge_index: 3,200,000 (int32) | batch: 100,000 (int32)
//   W1/W2: 49,152 (first = W1) | b1/b2: 384 (first = b1)
// ---------------------------------------------------------------------------
extern "C" void kernel_launch(void* const* d_in, const int* in_sizes, int n_in,
                              void* d_out, int out_size) {
    const float *x_in = nullptr, *W1 = nullptr, *b1 = nullptr, *W2 = nullptr, *b2 = nullptr;
    const int *ei = nullptr, *batch = nullptr;

    for (int i = 0; i < n_in; i++) {
        int s = in_sizes[i];
        if (s == N_NODES * D)            x_in  = (const float*)d_in[i];
        else if (s == 2 * N_EDGES)       ei    = (const int*)d_in[i];
        else if (s == N_NODES)           batch = (const int*)d_in[i];
        else if (s == N_LAYERS * D * D) { if (!W1) W1 = (const float*)d_in[i]; else W2 = (const float*)d_in[i]; }
        else if (s == N_LAYERS * D)     { if (!b1) b1 = (const float*)d_in[i]; else b2 = (const float*)d_in[i]; }
    }
    float* out = (float*)d_out;

    float* xa;   cudaGetSymbolAddress((void**)&xa,   g_xa);
    float* xcur; cudaGetSymbolAddress((void**)&xcur, g_xcur);
    int* counts;   cudaGetSymbolAddress((void**)&counts,   g_counts);
    int* rowstart; cudaGetSymbolAddress((void**)&rowstart, g_rowstart);
    int* cursor;   cudaGetSymbolAddress((void**)&cursor,   g_cursor);
    int* csr_src;  cudaGetSymbolAddress((void**)&csr_src,  g_csr_src);

    cudaFuncSetAttribute(mlp_kernel, cudaFuncAttributeMaxDynamicSharedMemorySize,
                         MLP_SMEM_BYTES);

    const int edge_blocks = (N_EDGES + 255) / 256;
    const int gemm_blocks = (N_NODES + 127) / 128;
    const int gat_blocks  = (N_NODES * 32 + 255) / 256;

    // CSR build (per call; deterministic structure)
    cudaMemsetAsync(counts, 0, N_NODES * sizeof(int));
    hist_kernel<<<edge_blocks, 256>>>(ei, counts);
    scan_kernel<<<1, 1024>>>(counts, rowstart, cursor);
    fill_kernel<<<edge_blocks, 256>>>(ei, cursor, csr_src);

    const float* xsrc = x_in;
    for (int i = 0; i < N_LAYERS; i++) {
        gather_kernel<<<gat_blocks, 256>>>(xsrc, rowstart, csr_src, xa);
        mlp_kernel<<<gemm_blocks, MLP_THREADS, MLP_SMEM_BYTES>>>(
            xa, W1 + (size_t)i * D * D, b1 + i * D,
            W2 + (size_t)i * D * D, b2 + i * D, xcur, N_NODES);
        xsrc = xcur;
    }

    cudaMemsetAsync(out, 0, (size_t)N_GRAPHS * D * sizeof(float));
    pool_kernel<<<400, 128>>>(xcur, batch, out);
}